// round 4
// baseline (speedup 1.0000x reference)
#include <cuda_runtime.h>
#include <cstdint>

// Problem constants (fixed shapes)
#define BATCH 8
#define CH    128
#define HH    160
#define WW    288
#define SR    4            // search range
#define ND    81           // (2*SR+1)^2

// Tiling
#define TY    8            // tile rows
#define TX    32           // tile cols
#define KC    4            // channels per stage
#define NSTAGE (CH / KC)   // 32
#define THREADS 192        // 3 dy-groups * 64 spatial slots
#define TROWS (TY + 2*SR)  // 16 tgt rows incl halo
#define TCOLS (TX + 2*SR)  // 40 tgt cols incl halo
#define SSTRIDE 40         // shared row stride (floats) for both tiles

// ---------------------------------------------------------------------------
// channel index for displacement (dy,dx), matching the reference ordering:
// ch0=(0,0); per i: (-i,0),(i,0),(0,-i),(0,i); then per j: (-i,-j),(i,j),(-i,j),(i,-j)
// ---------------------------------------------------------------------------
__device__ __forceinline__ int chan_of(int dy, int dx) {
    if (dy == 0 && dx == 0) return 0;
    if (dx == 0) { int i = abs(dy); return 1 + (i - 1) * 20 + (dy < 0 ? 0 : 1); }
    if (dy == 0) { int i = abs(dx); return 1 + (i - 1) * 20 + (dx < 0 ? 2 : 3); }
    int i = abs(dy), j = abs(dx);
    int q = (dy < 0) ? (dx < 0 ? 0 : 2) : (dx < 0 ? 3 : 1);
    return 1 + (i - 1) * 20 + 4 + (j - 1) * 4 + q;
}

__device__ __forceinline__ void cp_async4(uint32_t smem, const void* gmem) {
    asm volatile("cp.async.ca.shared.global [%0], [%1], 4;\n" :: "r"(smem), "l"(gmem));
}
__device__ __forceinline__ void cp_commit() {
    asm volatile("cp.async.commit_group;\n" ::: "memory");
}
__device__ __forceinline__ void cp_wait1() {
    asm volatile("cp.async.wait_group 1;\n" ::: "memory");
}
__device__ __forceinline__ void cp_wait0() {
    asm volatile("cp.async.wait_group 0;\n" ::: "memory");
}

__global__ void __launch_bounds__(THREADS, 2)
cost_volume_kernel(const float* __restrict__ src,
                   const float* __restrict__ tgt,
                   float* __restrict__ out)
{
    __shared__ __align__(16) float sh_tgt[2][KC][TROWS][SSTRIDE]; // 20480 B
    __shared__ __align__(16) float sh_src[2][KC][TY][SSTRIDE];    // 10240 B

    const int tid = threadIdx.x;
    const int g   = tid >> 6;          // dy-group 0..2
    const int pos = tid & 63;
    const int ty  = pos >> 3;          // 0..7 (quarter-warp = fixed ty)
    const int txg = pos & 7;           // 0..7 x-group of 4

    const int x0 = blockIdx.x * TX;
    const int y0 = blockIdx.y * TY;
    const int b  = blockIdx.z;

    // base pointers for this batch
    const float* srcb = src + (size_t)b * CH * HH * WW;
    const float* tgtb = tgt + (size_t)b * CH * HH * WW;

    float acc[3][9][4];
#pragma unroll
    for (int r = 0; r < 3; r++)
#pragma unroll
        for (int d = 0; d < 9; d++)
#pragma unroll
            for (int k = 0; k < 4; k++) acc[r][d][k] = 0.f;

    // ------------------------------------------------------------------
    // stage loader: fills buffer bb with channels [s*KC, s*KC+KC)
    // ------------------------------------------------------------------
    auto load_stage = [&](int s, int bb) {
        const int c0 = s * KC;
        // tgt with halo + zero border: KC * 16 * 40 = 2560 elems
#pragma unroll 1
        for (int i = tid; i < KC * TROWS * TCOLS; i += THREADS) {
            int cc  = i / (TROWS * TCOLS);
            int rem = i - cc * (TROWS * TCOLS);
            int r   = rem / TCOLS;
            int col = rem - r * TCOLS;
            int gy = y0 - SR + r;
            int gx = x0 - SR + col;
            float* sp = &sh_tgt[bb][cc][r][col];
            if ((unsigned)gy < (unsigned)HH && (unsigned)gx < (unsigned)WW) {
                uint32_t sa = (uint32_t)__cvta_generic_to_shared(sp);
                cp_async4(sa, &tgtb[((size_t)(c0 + cc) * HH + gy) * WW + gx]);
            } else {
                *sp = 0.f;
            }
        }
        // src tile (always in range; tiles divide H and W exactly): KC*8*32 = 1024
#pragma unroll 1
        for (int i = tid; i < KC * TY * TX; i += THREADS) {
            int cc  = i / (TY * TX);
            int rem = i - cc * (TY * TX);
            int r   = rem >> 5;
            int col = rem & 31;
            float* sp = &sh_src[bb][cc][r][col];
            uint32_t sa = (uint32_t)__cvta_generic_to_shared(sp);
            cp_async4(sa, &srcb[((size_t)(c0 + cc) * HH + (y0 + r)) * WW + (x0 + col)]);
        }
        cp_commit();
    };

    load_stage(0, 0);

    const int trow0 = ty + g * 3;  // tgt row for rr=0:  ty + 4 + (g*3 + 0 - 4)
    const int scol  = txg * 4;

#pragma unroll 1
    for (int s = 0; s < NSTAGE; s++) {
        const int buf = s & 1;
        if (s + 1 < NSTAGE) {
            load_stage(s + 1, buf ^ 1);
            cp_wait1();
        } else {
            cp_wait0();
        }
        __syncthreads();

#pragma unroll
        for (int cc = 0; cc < KC; cc++) {
            const float4 sv = *(const float4*)&sh_src[buf][cc][ty][scol];
            const float* tp = &sh_tgt[buf][cc][trow0][scol];
#pragma unroll
            for (int rr = 0; rr < 3; rr++) {
                const float4 ta = *(const float4*)(tp + rr * SSTRIDE);
                const float4 tb = *(const float4*)(tp + rr * SSTRIDE + 4);
                const float4 tc = *(const float4*)(tp + rr * SSTRIDE + 8);
                float t[12] = {ta.x, ta.y, ta.z, ta.w,
                               tb.x, tb.y, tb.z, tb.w,
                               tc.x, tc.y, tc.z, tc.w};
#pragma unroll
                for (int dxi = 0; dxi < 9; dxi++) {
                    acc[rr][dxi][0] = fmaf(sv.x, t[dxi + 0], acc[rr][dxi][0]);
                    acc[rr][dxi][1] = fmaf(sv.y, t[dxi + 1], acc[rr][dxi][1]);
                    acc[rr][dxi][2] = fmaf(sv.z, t[dxi + 2], acc[rr][dxi][2]);
                    acc[rr][dxi][3] = fmaf(sv.w, t[dxi + 3], acc[rr][dxi][3]);
                }
            }
        }
        __syncthreads();
    }

    // ------------------------------------------------------------------
    // Epilogue: scale by 1/C and write the 27 (dy,dx) channels this thread owns
    // ------------------------------------------------------------------
    const float scale = 1.0f / (float)CH;
    const int y = y0 + ty;
    const int x = x0 + txg * 4;
#pragma unroll
    for (int rr = 0; rr < 3; rr++) {
        const int dy = g * 3 + rr - SR;
#pragma unroll
        for (int dxi = 0; dxi < 9; dxi++) {
            const int dx = dxi - SR;
            const int ch = chan_of(dy, dx);
            float4 v;
            v.x = acc[rr][dxi][0] * scale;
            v.y = acc[rr][dxi][1] * scale;
            v.z = acc[rr][dxi][2] * scale;
            v.w = acc[rr][dxi][3] * scale;
            *(float4*)&out[(((size_t)b * ND + ch) * HH + y) * WW + x] = v;
        }
    }
}

extern "C" void kernel_launch(void* const* d_in, const int* in_sizes, int n_in,
                              void* d_out, int out_size)
{
    const float* src = (const float*)d_in[0];
    const float* tgt = (const float*)d_in[1];
    float* out = (float*)d_out;

    dim3 grid(WW / TX, HH / TY, BATCH);   // (9, 20, 8) = 1440 blocks
    cost_volume_kernel<<<grid, THREADS>>>(src, tgt, out);
}

// round 6
// speedup vs baseline: 1.8760x; 1.8760x over previous
#include <cuda_runtime.h>
#include <cstdint>

// Problem constants (fixed shapes)
#define BATCH 8
#define CH    128
#define HH    160
#define WW    288
#define SR    4
#define ND    81

// Tiling
#define TY    8
#define TX    32
#define KC    4
#define NSTAGE (CH / KC)       // 32
#define THREADS 192            // 3 dy-groups * 64 spatial slots
#define TROWS (TY + 2*SR)      // 16
#define TCOLS (TX + 2*SR)      // 40
#define SSTRIDE 40             // shared row stride (floats)

#define STAGE_BYTES (KC * HH * WW * 4)          // 737280 bytes per KC-channel stage
#define TGT_BUF_BYTES (KC * TROWS * SSTRIDE * 4) // 10240
#define SRC_BUF_BYTES (KC * TY * SSTRIDE * 4)    // 5120
#define TGT_F4 (KC * TROWS * 10)                 // 640 float4 per stage
#define SRC_F4 (KC * TY * 8)                     // 256 float4 per stage

// ---------------------------------------------------------------------------
// channel index for displacement (dy,dx), matching the reference ordering
// ---------------------------------------------------------------------------
__device__ __forceinline__ int chan_of(int dy, int dx) {
    if (dy == 0 && dx == 0) return 0;
    if (dx == 0) { int i = abs(dy); return 1 + (i - 1) * 20 + (dy < 0 ? 0 : 1); }
    if (dy == 0) { int i = abs(dx); return 1 + (i - 1) * 20 + (dx < 0 ? 2 : 3); }
    int i = abs(dy), j = abs(dx);
    int q = (dy < 0) ? (dx < 0 ? 0 : 2) : (dx < 0 ? 3 : 1);
    return 1 + (i - 1) * 20 + 4 + (j - 1) * 4 + q;
}

__device__ __forceinline__ void cp_async16_sz(uint32_t smem, const void* gmem, uint32_t sz) {
    asm volatile("cp.async.cg.shared.global [%0], [%1], 16, %2;\n"
                 :: "r"(smem), "l"(gmem), "r"(sz));
}
__device__ __forceinline__ void cp_async16(uint32_t smem, const void* gmem) {
    asm volatile("cp.async.cg.shared.global [%0], [%1], 16;\n"
                 :: "r"(smem), "l"(gmem));
}
__device__ __forceinline__ void cp_commit() {
    asm volatile("cp.async.commit_group;\n" ::: "memory");
}
__device__ __forceinline__ void cp_wait1() {
    asm volatile("cp.async.wait_group 1;\n" ::: "memory");
}
__device__ __forceinline__ void cp_wait0() {
    asm volatile("cp.async.wait_group 0;\n" ::: "memory");
}

__global__ void __launch_bounds__(THREADS, 2)
cost_volume_kernel(const float* __restrict__ src,
                   const float* __restrict__ tgt,
                   float* __restrict__ out)
{
    __shared__ __align__(16) float sh_tgt[2][KC][TROWS][SSTRIDE]; // 20480 B
    __shared__ __align__(16) float sh_src[2][KC][TY][SSTRIDE];    // 10240 B

    const int tid = threadIdx.x;
    const int g   = tid >> 6;          // dy-group 0..2
    const int pos = tid & 63;
    const int ty  = pos >> 3;          // 0..7
    const int txg = pos & 7;           // 0..7

    const int x0 = blockIdx.x * TX;
    const int y0 = blockIdx.y * TY;
    const int b  = blockIdx.z;

    const char* srcb = (const char*)(src + (size_t)b * CH * HH * WW);
    const char* tgtb = (const char*)(tgt + (size_t)b * CH * HH * WW);

    const uint32_t tgt_smem_base = (uint32_t)__cvta_generic_to_shared(&sh_tgt[0][0][0][0]);
    const uint32_t src_smem_base = (uint32_t)__cvta_generic_to_shared(&sh_src[0][0][0][0]);

    // ------------------------------------------------------------------
    // Precompute loader slots ONCE (fixed shapes). Each thread owns up to
    // 4 tgt float4 and 2 src float4 per stage. Halo/border float4s are
    // never partially OOB (W, x0, halo all 16B-aligned multiples of 4).
    // ------------------------------------------------------------------
    uint32_t t_sm[4], t_go[4], t_sz[4];
    const int n_t = (tid < TGT_F4 - 3 * THREADS) ? 4 : 3;   // tid<64 -> 4
#pragma unroll
    for (int sl = 0; sl < 4; sl++) {
        int i = tid + sl * THREADS;
        if (i >= TGT_F4) i = 0;        // dummy for inactive slot (never issued)
        int cc  = i / (TROWS * 10);
        int rem = i - cc * (TROWS * 10);
        int r   = rem / 10;
        int c4  = rem - r * 10;
        int gy = y0 - SR + r;
        int gx = x0 - SR + c4 * 4;
        bool valid = ((unsigned)gy < (unsigned)HH) && ((unsigned)gx <= (unsigned)(WW - 4));
        t_sm[sl] = tgt_smem_base + (uint32_t)(((cc * TROWS + r) * SSTRIDE + c4 * 4) * 4);
        t_go[sl] = valid ? (uint32_t)(((cc * HH + gy) * WW + gx) * 4) : 0u;
        t_sz[sl] = valid ? 16u : 0u;   // sz=0 -> cp.async zero-fills 16B
    }

    uint32_t s_sm[2], s_go[2];
    const int n_s = (tid < SRC_F4 - THREADS) ? 2 : 1;       // tid<64 -> 2
#pragma unroll
    for (int sl = 0; sl < 2; sl++) {
        int i = tid + sl * THREADS;
        if (i >= SRC_F4) i = 0;
        int cc  = i >> 6;              // / (TY*8)
        int rem = i & 63;
        int r   = rem >> 3;
        int c4  = rem & 7;
        s_sm[sl] = src_smem_base + (uint32_t)(((cc * TY + r) * SSTRIDE + c4 * 4) * 4);
        s_go[sl] = (uint32_t)(((cc * HH + (y0 + r)) * WW + (x0 + c4 * 4)) * 4);
    }

    float acc[3][9][4];
#pragma unroll
    for (int r = 0; r < 3; r++)
#pragma unroll
        for (int d = 0; d < 9; d++)
#pragma unroll
            for (int k = 0; k < 4; k++) acc[r][d][k] = 0.f;

    // ------------------------------------------------------------------
    // stage loader: pure pointer-add + predicated LDGSTS.128
    // ------------------------------------------------------------------
    auto load_stage = [&](uint32_t goff, int bb) {
        const uint32_t tb = (uint32_t)bb * TGT_BUF_BYTES;
        const uint32_t sb = (uint32_t)bb * SRC_BUF_BYTES;
#pragma unroll
        for (int sl = 0; sl < 4; sl++)
            if (sl < n_t)
                cp_async16_sz(t_sm[sl] + tb, tgtb + t_go[sl] + goff, t_sz[sl]);
#pragma unroll
        for (int sl = 0; sl < 2; sl++)
            if (sl < n_s)
                cp_async16(s_sm[sl] + sb, srcb + s_go[sl] + goff);
        cp_commit();
    };

    load_stage(0, 0);

    const int trow0 = ty + g * 3;
    const int scol  = txg * 4;

    uint32_t stage_off = 0;
#pragma unroll 1
    for (int s = 0; s < NSTAGE; s++) {
        const int buf = s & 1;
        if (s + 1 < NSTAGE) {
            load_stage(stage_off + STAGE_BYTES, buf ^ 1);
            cp_wait1();
        } else {
            cp_wait0();
        }
        __syncthreads();

#pragma unroll
        for (int cc = 0; cc < KC; cc++) {
            const float4 sv = *(const float4*)&sh_src[buf][cc][ty][scol];
            const float* tp = &sh_tgt[buf][cc][trow0][scol];
#pragma unroll
            for (int rr = 0; rr < 3; rr++) {
                const float4 ta = *(const float4*)(tp + rr * SSTRIDE);
                const float4 tb4 = *(const float4*)(tp + rr * SSTRIDE + 4);
                const float4 tc4 = *(const float4*)(tp + rr * SSTRIDE + 8);
                float t[12] = {ta.x, ta.y, ta.z, ta.w,
                               tb4.x, tb4.y, tb4.z, tb4.w,
                               tc4.x, tc4.y, tc4.z, tc4.w};
#pragma unroll
                for (int dxi = 0; dxi < 9; dxi++) {
                    acc[rr][dxi][0] = fmaf(sv.x, t[dxi + 0], acc[rr][dxi][0]);
                    acc[rr][dxi][1] = fmaf(sv.y, t[dxi + 1], acc[rr][dxi][1]);
                    acc[rr][dxi][2] = fmaf(sv.z, t[dxi + 2], acc[rr][dxi][2]);
                    acc[rr][dxi][3] = fmaf(sv.w, t[dxi + 3], acc[rr][dxi][3]);
                }
            }
        }
        __syncthreads();
        stage_off += STAGE_BYTES;
    }

    // ------------------------------------------------------------------
    // Epilogue: scale by 1/C and write the 27 (dy,dx) channels this thread owns
    // ------------------------------------------------------------------
    const float scale = 1.0f / (float)CH;
    const int y = y0 + ty;
    const int x = x0 + txg * 4;
#pragma unroll
    for (int rr = 0; rr < 3; rr++) {
        const int dy = g * 3 + rr - SR;
#pragma unroll
        for (int dxi = 0; dxi < 9; dxi++) {
            const int dx = dxi - SR;
            const int ch = chan_of(dy, dx);
            float4 v;
            v.x = acc[rr][dxi][0] * scale;
            v.y = acc[rr][dxi][1] * scale;
            v.z = acc[rr][dxi][2] * scale;
            v.w = acc[rr][dxi][3] * scale;
            *(float4*)&out[(((size_t)b * ND + ch) * HH + y) * WW + x] = v;
        }
    }
}

extern "C" void kernel_launch(void* const* d_in, const int* in_sizes, int n_in,
                              void* d_out, int out_size)
{
    const float* src = (const float*)d_in[0];
    const float* tgt = (const float*)d_in[1];
    float* out = (float*)d_out;

    dim3 grid(WW / TX, HH / TY, BATCH);   // (9, 20, 8) = 1440 blocks
    cost_volume_kernel<<<grid, THREADS>>>(src, tgt, out);
}